// round 15
// baseline (speedup 1.0000x reference)
#include <cuda_runtime.h>
#include <cuda_fp16.h>
#include <math.h>
#include <stdint.h>

#define SZ     4096
#define SEN    128
#define DC     128
#define OUTD   984
#define CCONST 160
#define GS     8
#define KT     21             // k16 steps = 3 taps * 7
#define VROWB  240            // bytes per v-tile row: 120 halves (112 data + 8 pad)
#define VH_BYTES (130 * VROWB)   // 31200 per sample tile (rows x = 0..129)
#define NSTREAM 296           // 148 CTAs * 2 groups

// SMEM byte offsets
#define SMB_B    0                      // 21*8*32 uint4 = 86016
#define SMB_VH   86016                  // 4 tiles (g,buf) * 31200 = 124800 -> 210816
#define SMB_MASK 210816                 // 4 * 384 half = 3072 -> 213888
#define SMB_CB   213888                 // 4 * 384 f = 6144 -> 220032
#define SMB_TOT  220032

typedef unsigned long long u64;

__device__ __align__(16) uint32_t gBfh[KT * 8 * 32 * 4];   // fp16 B frags, uint4-grouped
__device__ __align__(16) float gW2[3 * CCONST * DC];
__device__ __align__(16) float gBase[SZ * 3 * DC];

__device__ __forceinline__ uint32_t smem_u32(const void* p) {
    uint32_t a;
    asm("{ .reg .u64 t; cvta.to.shared.u64 t, %1; cvt.u32.u64 %0, t; }" : "=r"(a) : "l"(p));
    return a;
}
#define CP16(dst_u32, src_ptr) \
    asm volatile("cp.async.cg.shared.global [%0], [%1], 16;" :: "r"(dst_u32), "l"(src_ptr) : "memory")
#define CP_COMMIT() asm volatile("cp.async.commit_group;" ::: "memory")
#define CP_WAIT0()  asm volatile("cp.async.wait_group 0;" ::: "memory")
#define BAR_G(id) asm volatile("bar.sync %0, 256;" :: "r"(id) : "memory")
#define LDSM4(r0, r1, r2, r3, addr) \
    asm volatile("ldmatrix.sync.aligned.m8n8.x4.shared.b16 {%0,%1,%2,%3}, [%4];" \
        : "=r"(r0), "=r"(r1), "=r"(r2), "=r"(r3) : "r"(addr))
#define MMA_F16(d, a0, a1, a2, a3, bx, by) \
    asm volatile("mma.sync.aligned.m16n8k16.row.col.f32.f16.f16.f32 " \
        "{%0,%1,%2,%3},{%4,%5,%6,%7},{%8,%9},{%0,%1,%2,%3};" \
        : "+f"(d[0]), "+f"(d[1]), "+f"(d[2]), "+f"(d[3]) \
        : "r"(a0), "r"(a1), "r"(a2), "r"(a3), "r"(bx), "r"(by))

// ============================================================================
// P0: fp16 B fragments grouped for LDS.128 (unchanged layout) + gW2.
// ============================================================================
__global__ void prep_kernel(const float* __restrict__ conv_w) {
    int idx = blockIdx.x * blockDim.x + threadIdx.x;
    if (idx < KT * 16 * 32 * 2) {
        int r = idx & 1, lane = (idx >> 1) & 31, nt = (idx >> 6) & 15, kt = idx >> 10;
        int o = nt * 8 + (lane >> 2);
        int j0 = kt * 16 + (lane & 3) * 2 + r * 8;
        float v0 = 0.f, v1 = 0.f;
        { int tap = j0 / 112, c = j0 % 112; if (c < 110) v0 = conv_w[o * 810 + c * 3 + tap]; }
        { int j1 = j0 + 1; int tap = j1 / 112, c = j1 % 112; if (c < 110) v1 = conv_w[o * 810 + c * 3 + tap]; }
        __half2 h = __floats2half2_rn(v0, v1);
        gBfh[((kt * 8 + (nt >> 1)) * 32 + lane) * 4 + (nt & 1) * 2 + r] = *(uint32_t*)&h;
    } else {
        int i2 = idx - KT * 16 * 32 * 2;
        if (i2 < 3 * CCONST * DC) {
            int kc = i2 / DC, o = i2 % DC;
            int k = kc / CCONST, c2 = kc % CCONST;
            gW2[i2] = conv_w[o * 810 + (110 + c2) * 3 + k];
        }
    }
}

// ============================================================================
// P1: constant-channel base + loc branch (exact fp32, unchanged).
// ============================================================================
__global__ __launch_bounds__(256) void const_kernel(
    const int* __restrict__ loc, const int* __restrict__ loc_mark,
    const int* __restrict__ subtype, const int* __restrict__ argRole,
    const float* __restrict__ word_emb, const float* __restrict__ event_emb,
    const float* __restrict__ role_emb, float* __restrict__ out)
{
    __shared__ float evrl[GS][CCONST];
    int tid = threadIdx.x;
    int b0 = blockIdx.x * GS;
    for (int i = tid; i < GS * CCONST; i += 256) {
        int g = i / CCONST, c2 = i % CCONST;
        int b = b0 + g;
        float v;
        if (c2 < 32) v = event_emb[subtype[b] * 32 + c2];
        else { int r = (c2 - 32) >> 4, q = (c2 - 32) & 15; v = role_emb[argRole[b * 8 + r] * 16 + q]; }
        evrl[g][c2] = v;
    }
    __syncthreads();
    for (int t = tid; t < 3 * DC; t += 256) {
        int o = t % DC, k = t / DC;
        float s[GS];
        #pragma unroll
        for (int g = 0; g < GS; g++) s[g] = 0.f;
        const float* w2 = &gW2[k * CCONST * DC + o];
        for (int c2 = 0; c2 < CCONST; c2++) {
            float w = w2[c2 * DC];
            #pragma unroll
            for (int g = 0; g < GS; g++) s[g] = fmaf(evrl[g][c2], w, s[g]);
        }
        #pragma unroll
        for (int g = 0; g < GS; g++) gBase[(size_t)(b0 + g) * (3 * DC) + t] = s[g];
    }
    int g = tid >> 5, lane = tid & 31;
    int b = b0 + g;
    const int* lb = &loc[b * 16];
    int mark = loc_mark[b];
    float* ob = &out[(size_t)b * OUTD + 384];
    for (int d = lane; d < 100; d += 32) {
        #pragma unroll
        for (int i = 0; i < 4; i++) ob[i * 100 + d] = tanhf(word_emb[lb[i] * 100 + d]);
        float s = 0.f;
        for (int i = 0; i < mark; i++) s += word_emb[lb[4 + i] * 100 + d];
        ob[400 + d] = tanhf(s / (float)mark);
        ob[500 + d] = tanhf(word_emb[lb[4 + mark] * 100 + d]);
    }
}

// ============================================================================
// v-tile gather for ONE sample into tile slot `slot` (256-thread group).
// ============================================================================
__device__ __forceinline__ void gather_sample(
    char* smb, int b, int slot, int tid_g,
    const int* __restrict__ inp, const int* __restrict__ pos1, const int* __restrict__ pos2,
    const float* __restrict__ word_emb, const float* __restrict__ pos_emb)
{
    char* base = smb + SMB_VH + slot * VH_BYTES;
    const int* inpb = inp + b * SEN;
    for (int idx = tid_g; idx < SEN * 25; idx += 256) {
        int s = idx / 25, q4 = idx % 25;
        float4 w4 = ((const float4*)word_emb)[(size_t)inpb[s] * 25 + q4];
        __half2 h01 = __floats2half2_rn(w4.x, w4.y);
        __half2 h23 = __floats2half2_rn(w4.z, w4.w);
        uint2 val = make_uint2(*(uint32_t*)&h01, *(uint32_t*)&h23);
        *(uint2*)(base + (s + 1) * VROWB + q4 * 8) = val;
    }
    const int* p1b = pos1 + b * SEN;
    const int* p2b = pos2 + b * SEN;
    for (int idx = tid_g; idx < SEN * 10; idx += 256) {
        int s = idx / 10, r = idx % 10;
        int row = (r < 5) ? p1b[s] : p2b[s];
        *(__half*)(base + (s + 1) * VROWB + (100 + r) * 2) =
            __float2half_rn(pos_emb[row * 5 + (r % 5)]);
    }
}

// ============================================================================
// stage masks (half 0/1 — exact) + combined bias for ONE sample, slot `slot`.
// ============================================================================
__device__ __forceinline__ void stage_sample(
    char* smb, int b, int slot, int tid_g,
    const float* __restrict__ maskL, const float* __restrict__ maskM,
    const float* __restrict__ maskR, const float* __restrict__ conv_b)
{
    __half* mdst = (__half*)(smb + SMB_MASK) + slot * 384;
    for (int i = tid_g; i < 3 * SEN; i += 256) {
        float v = (i < 128) ? maskL[b * SEN + i]
                : (i < 256) ? maskM[b * SEN + i - 128]
                            : maskR[b * SEN + i - 256];
        mdst[i] = __float2half_rn(v);
    }
    float* cb = (float*)(smb + SMB_CB) + slot * 384;
    if (tid_g < DC) {
        float b0v = gBase[(size_t)b * 384 + tid_g];
        float b1v = gBase[(size_t)b * 384 + 128 + tid_g];
        float b2v = gBase[(size_t)b * 384 + 256 + tid_g];
        cb[tid_g]       = conv_b[tid_g] + b0v + b1v + b2v;
        cb[128 + tid_g] = b0v;
        cb[256 + tid_g] = b2v;
    }
}

// ============================================================================
// Main: 148 persistent CTAs (512 thr), TWO independent 8-warp groups, each its
// own sample stream + double buffers. Warp tile m128 x n16 (1(M) x 8(N) grid):
// every warp owns all 128 s-rows of its 16 o-cols -> epilogue is warp-local
// (register fmax + 3 shfls, direct gmem write). ONE barrier per iteration.
// ============================================================================
__global__ __launch_bounds__(512, 1) void main_kernel(
    const int* __restrict__ inp, const int* __restrict__ pos1, const int* __restrict__ pos2,
    const float* __restrict__ maskL, const float* __restrict__ maskM, const float* __restrict__ maskR,
    const float* __restrict__ word_emb, const float* __restrict__ pos_emb,
    const float* __restrict__ conv_b, float* __restrict__ out)
{
    extern __shared__ char smb[];

    const int tid = threadIdx.x;
    const int lane = tid & 31, warp = tid >> 5;
    const int g = (warp >> 2) & 1;                    // group (spans all 4 SMSPs)
    const int wn = (warp >> 3) * 4 + (warp & 3);      // 0..7: n16 slice within group
    const int tid_g = wn * 32 + lane;                 // 0..255 within group
    const uint32_t smb_u = smem_u32(smb);

    // ---- one-time (all 512): load B (84KB), zero all 4 v tiles ----
    {
        uint32_t dst = smb_u + SMB_B;
        const uint32_t* src = gBfh;
        for (int i = tid; i < KT * 8 * 32 * 4 / 4; i += 512)
            CP16(dst + i * 16, src + i * 4);
        CP_COMMIT();
    }
    for (int i = tid; i < 4 * VH_BYTES / 4; i += 512)
        ((uint32_t*)(smb + SMB_VH))[i] = 0u;
    CP_WAIT0();
    __syncthreads();   // last CTA-wide barrier; groups diverge below

    // ---- per-group: gather+stage first sample into slot (g*2 + 0) ----
    const int b0 = blockIdx.x * 2 + g;
    gather_sample(smb, b0, g * 2, tid_g, inp, pos1, pos2, word_emb, pos_emb);
    stage_sample(smb, b0, g * 2, tid_g, maskL, maskM, maskR, conv_b);

    // ldmatrix lane addr part: row (lane&15), k-half block (lane>>4)*16B
    const uint32_t rowsel = (uint32_t)((lane & 15) * VROWB + ((lane >> 4) << 4));
    const int barid = g + 1;

    int itg = 0;
    for (int b = b0; b < SZ; b += NSTREAM, ++itg) {
        const int cur = itg & 1;
        const int slot = g * 2 + cur;

        BAR_G(barid);   // B1: sample b resident in slot (sole barrier per iter)

        // ---- prefetch next sample (unsynced; due by next B1) ----
        if (b + NSTREAM < SZ) {
            gather_sample(smb, b + NSTREAM, g * 2 + (cur ^ 1), tid_g, inp, pos1, pos2, word_emb, pos_emb);
            stage_sample(smb, b + NSTREAM, g * 2 + (cur ^ 1), tid_g, maskL, maskM, maskR, conv_b);
        }

        // ---- GEMM mainloop: m128 x n16 per warp (8 m-tiles x 2 n-tiles) ----
        float acc[8][2][4];
        #pragma unroll
        for (int mt = 0; mt < 8; mt++)
            #pragma unroll
            for (int nt = 0; nt < 2; nt++)
                #pragma unroll
                for (int r = 0; r < 4; r++) acc[mt][nt][r] = 0.f;

        const uint32_t vb = smb_u + SMB_VH + slot * VH_BYTES + rowsel;
        const uint4* sB4 = (const uint4*)(smb + SMB_B);

        #pragma unroll
        for (int tap = 0; tap < 3; tap++) {
            #pragma unroll
            for (int ktl = 0; ktl < 7; ktl++) {
                const int kt = tap * 7 + ktl;
                const uint32_t roff = (uint32_t)(tap * VROWB + ktl * 32);
                const uint4 bb = (sB4 + kt * 256 + wn * 32)[lane];
                // two halves of 4 m-tiles each to bound register pressure
                #pragma unroll
                for (int hlf = 0; hlf < 2; hlf++) {
                    uint32_t am[4][4];
                    #pragma unroll
                    for (int q = 0; q < 4; q++) {
                        int mt = hlf * 4 + q;
                        LDSM4(am[q][0], am[q][1], am[q][2], am[q][3],
                              vb + roff + (uint32_t)(mt * 16 * VROWB));
                    }
                    #pragma unroll
                    for (int q = 0; q < 4; q++) {
                        int mt = hlf * 4 + q;
                        MMA_F16(acc[mt][0], am[q][0], am[q][1], am[q][2], am[q][3], bb.x, bb.y);
                        MMA_F16(acc[mt][1], am[q][0], am[q][1], am[q][2], am[q][3], bb.z, bb.w);
                    }
                }
            }
        }

        // ---- warp-local epilogue (no barrier, no smem partials) ----
        {
            const __half* mp = (const __half*)(smb + SMB_MASK) + slot * 384;
            const float* cb = (const float*)(smb + SMB_CB) + slot * 384;
            float C[2][2], B0v[2][2], B2v[2][2];
            #pragma unroll
            for (int nt = 0; nt < 2; nt++)
                #pragma unroll
                for (int h = 0; h < 2; h++) {
                    int o = wn * 16 + nt * 8 + 2 * (lane & 3) + h;
                    C[nt][h]   = cb[o];
                    B0v[nt][h] = cb[128 + o];
                    B2v[nt][h] = cb[256 + o];
                }
            float p[3][2][2];
            #pragma unroll
            for (int m = 0; m < 3; m++)
                #pragma unroll
                for (int nt = 0; nt < 2; nt++)
                    #pragma unroll
                    for (int h = 0; h < 2; h++) p[m][nt][h] = -3.0e38f;

            #pragma unroll
            for (int mt = 0; mt < 8; mt++)
                #pragma unroll
                for (int rg = 0; rg < 2; rg++) {
                    int s = mt * 16 + (lane >> 2) + rg * 8;
                    float m0 = __half2float(mp[s]);
                    float m1 = __half2float(mp[128 + s]);
                    float m2 = __half2float(mp[256 + s]);
                    #pragma unroll
                    for (int nt = 0; nt < 2; nt++)
                        #pragma unroll
                        for (int h = 0; h < 2; h++) {
                            float cv = acc[mt][nt][rg * 2 + h] + C[nt][h];
                            if (s == 0)   cv -= B0v[nt][h];
                            if (s == 127) cv -= B2v[nt][h];
                            p[0][nt][h] = fmaxf(p[0][nt][h], cv * m0);
                            p[1][nt][h] = fmaxf(p[1][nt][h], cv * m1);
                            p[2][nt][h] = fmaxf(p[2][nt][h], cv * m2);
                        }
                }
            // reduce over the 8 lanes sharing lane&3 (s-partition classes)
            #pragma unroll
            for (int m = 0; m < 3; m++)
                #pragma unroll
                for (int nt = 0; nt < 2; nt++)
                    #pragma unroll
                    for (int h = 0; h < 2; h++) {
                        float v = p[m][nt][h];
                        v = fmaxf(v, __shfl_xor_sync(0xffffffffu, v, 4));
                        v = fmaxf(v, __shfl_xor_sync(0xffffffffu, v, 8));
                        v = fmaxf(v, __shfl_xor_sync(0xffffffffu, v, 16));
                        p[m][nt][h] = v;
                    }
            if (lane < 4) {
                float* ob = out + (size_t)b * OUTD;
                #pragma unroll
                for (int m = 0; m < 3; m++)
                    #pragma unroll
                    for (int nt = 0; nt < 2; nt++)
                        #pragma unroll
                        for (int h = 0; h < 2; h++) {
                            int o = wn * 16 + nt * 8 + 2 * lane + h;
                            ob[m * 128 + o] = tanhf(p[m][nt][h]);
                        }
            }
        }
        // next iteration's B1 orders everything
    }
}

// ============================================================================
extern "C" void kernel_launch(void* const* d_in, const int* in_sizes, int n_in,
                              void* d_out, int out_size) {
    const int*   inp       = (const int*)d_in[0];
    const int*   pos1      = (const int*)d_in[1];
    const int*   pos2      = (const int*)d_in[2];
    const int*   loc       = (const int*)d_in[3];
    const int*   loc_mark  = (const int*)d_in[4];
    const int*   subtype   = (const int*)d_in[5];
    const int*   argRole   = (const int*)d_in[6];
    const float* maskL     = (const float*)d_in[7];
    const float* maskM     = (const float*)d_in[8];
    const float* maskR     = (const float*)d_in[9];
    const float* word_emb  = (const float*)d_in[10];
    const float* pos_emb   = (const float*)d_in[11];
    const float* event_emb = (const float*)d_in[12];
    const float* role_emb  = (const float*)d_in[13];
    const float* conv_w    = (const float*)d_in[14];
    const float* conv_b    = (const float*)d_in[15];
    float* out = (float*)d_out;

    int prep_elems = KT * 16 * 32 * 2 + 3 * CCONST * DC;
    prep_kernel<<<(prep_elems + 255) / 256, 256>>>(conv_w);
    const_kernel<<<SZ / GS, 256>>>(loc, loc_mark, subtype, argRole,
                                   word_emb, event_emb, role_emb, out);
    cudaFuncSetAttribute(main_kernel, cudaFuncAttributeMaxDynamicSharedMemorySize, SMB_TOT);
    main_kernel<<<148, 512, SMB_TOT>>>(inp, pos1, pos2, maskL, maskM, maskR,
                                       word_emb, pos_emb, conv_b, out);
}

// round 16
// speedup vs baseline: 1.1123x; 1.1123x over previous
#include <cuda_runtime.h>
#include <cuda_fp16.h>
#include <math.h>
#include <stdint.h>

#define SZ     4096
#define SEN    128
#define DC     128
#define OUTD   984
#define CCONST 160
#define GS     8
#define KT     21             // k16 steps = 3 taps * 7
#define VROWB  240            // bytes per v-tile row: 120 halves (112 data + 8 pad)
#define VH_BYTES (130 * VROWB)   // 31200 per sample tile (rows x = 0..129)
#define NSTREAM 296           // 148 CTAs * 2 groups

// SMEM byte offsets
#define SMB_B    0                      // 21*8*32 uint4 = 86016
#define SMB_VH   86016                  // 4 tiles (g,buf) * 31200 = 124800 -> 210816
#define SMB_MASK 210816                 // 4 * 384 half = 3072 -> 213888
#define SMB_CB   213888                 // 4 * 384 f = 6144 -> 220032
#define SMB_R    220032                 // 2 groups * 2 bufs * 384*2 f = 12288 -> 232320
#define SMB_TOT  232320

typedef unsigned long long u64;

__device__ __align__(16) uint32_t gBfh[KT * 8 * 32 * 4];   // fp16 B frags, uint4-grouped
__device__ __align__(16) float gW2[3 * CCONST * DC];
__device__ __align__(16) float gBase[SZ * 3 * DC];

__device__ __forceinline__ uint32_t smem_u32(const void* p) {
    uint32_t a;
    asm("{ .reg .u64 t; cvta.to.shared.u64 t, %1; cvt.u32.u64 %0, t; }" : "=r"(a) : "l"(p));
    return a;
}
#define CP16(dst_u32, src_ptr) \
    asm volatile("cp.async.cg.shared.global [%0], [%1], 16;" :: "r"(dst_u32), "l"(src_ptr) : "memory")
#define CP_COMMIT() asm volatile("cp.async.commit_group;" ::: "memory")
#define CP_WAIT0()  asm volatile("cp.async.wait_group 0;" ::: "memory")
#define BAR_G(id) asm volatile("bar.sync %0, 256;" :: "r"(id) : "memory")
#define LDSM4(r0, r1, r2, r3, addr) \
    asm volatile("ldmatrix.sync.aligned.m8n8.x4.shared.b16 {%0,%1,%2,%3}, [%4];" \
        : "=r"(r0), "=r"(r1), "=r"(r2), "=r"(r3) : "r"(addr))
#define MMA_F16(d, a0, a1, a2, a3, bx, by) \
    asm volatile("mma.sync.aligned.m16n8k16.row.col.f32.f16.f16.f32 " \
        "{%0,%1,%2,%3},{%4,%5,%6,%7},{%8,%9},{%0,%1,%2,%3};" \
        : "+f"(d[0]), "+f"(d[1]), "+f"(d[2]), "+f"(d[3]) \
        : "r"(a0), "r"(a1), "r"(a2), "r"(a3), "r"(bx), "r"(by))

// ============================================================================
// P0: fp16 B fragments grouped for LDS.128 (unchanged layout) + gW2.
// ============================================================================
__global__ void prep_kernel(const float* __restrict__ conv_w) {
    int idx = blockIdx.x * blockDim.x + threadIdx.x;
    if (idx < KT * 16 * 32 * 2) {
        int r = idx & 1, lane = (idx >> 1) & 31, nt = (idx >> 6) & 15, kt = idx >> 10;
        int o = nt * 8 + (lane >> 2);
        int j0 = kt * 16 + (lane & 3) * 2 + r * 8;
        float v0 = 0.f, v1 = 0.f;
        { int tap = j0 / 112, c = j0 % 112; if (c < 110) v0 = conv_w[o * 810 + c * 3 + tap]; }
        { int j1 = j0 + 1; int tap = j1 / 112, c = j1 % 112; if (c < 110) v1 = conv_w[o * 810 + c * 3 + tap]; }
        __half2 h = __floats2half2_rn(v0, v1);
        gBfh[((kt * 8 + (nt >> 1)) * 32 + lane) * 4 + (nt & 1) * 2 + r] = *(uint32_t*)&h;
    } else {
        int i2 = idx - KT * 16 * 32 * 2;
        if (i2 < 3 * CCONST * DC) {
            int kc = i2 / DC, o = i2 % DC;
            int k = kc / CCONST, c2 = kc % CCONST;
            gW2[i2] = conv_w[o * 810 + (110 + c2) * 3 + k];
        }
    }
}

// ============================================================================
// P1: constant-channel base + loc branch (exact fp32, unchanged).
// ============================================================================
__global__ __launch_bounds__(256) void const_kernel(
    const int* __restrict__ loc, const int* __restrict__ loc_mark,
    const int* __restrict__ subtype, const int* __restrict__ argRole,
    const float* __restrict__ word_emb, const float* __restrict__ event_emb,
    const float* __restrict__ role_emb, float* __restrict__ out)
{
    __shared__ float evrl[GS][CCONST];
    int tid = threadIdx.x;
    int b0 = blockIdx.x * GS;
    for (int i = tid; i < GS * CCONST; i += 256) {
        int g = i / CCONST, c2 = i % CCONST;
        int b = b0 + g;
        float v;
        if (c2 < 32) v = event_emb[subtype[b] * 32 + c2];
        else { int r = (c2 - 32) >> 4, q = (c2 - 32) & 15; v = role_emb[argRole[b * 8 + r] * 16 + q]; }
        evrl[g][c2] = v;
    }
    __syncthreads();
    for (int t = tid; t < 3 * DC; t += 256) {
        int o = t % DC, k = t / DC;
        float s[GS];
        #pragma unroll
        for (int g = 0; g < GS; g++) s[g] = 0.f;
        const float* w2 = &gW2[k * CCONST * DC + o];
        for (int c2 = 0; c2 < CCONST; c2++) {
            float w = w2[c2 * DC];
            #pragma unroll
            for (int g = 0; g < GS; g++) s[g] = fmaf(evrl[g][c2], w, s[g]);
        }
        #pragma unroll
        for (int g = 0; g < GS; g++) gBase[(size_t)(b0 + g) * (3 * DC) + t] = s[g];
    }
    int g = tid >> 5, lane = tid & 31;
    int b = b0 + g;
    const int* lb = &loc[b * 16];
    int mark = loc_mark[b];
    float* ob = &out[(size_t)b * OUTD + 384];
    for (int d = lane; d < 100; d += 32) {
        #pragma unroll
        for (int i = 0; i < 4; i++) ob[i * 100 + d] = tanhf(word_emb[lb[i] * 100 + d]);
        float s = 0.f;
        for (int i = 0; i < mark; i++) s += word_emb[lb[4 + i] * 100 + d];
        ob[400 + d] = tanhf(s / (float)mark);
        ob[500 + d] = tanhf(word_emb[lb[4 + mark] * 100 + d]);
    }
}

// ============================================================================
// v-tile gather for ONE sample into tile slot `slot` (256-thread group).
// ============================================================================
__device__ __forceinline__ void gather_sample(
    char* smb, int b, int slot, int tid_g,
    const int* __restrict__ inp, const int* __restrict__ pos1, const int* __restrict__ pos2,
    const float* __restrict__ word_emb, const float* __restrict__ pos_emb)
{
    char* base = smb + SMB_VH + slot * VH_BYTES;
    const int* inpb = inp + b * SEN;
    for (int idx = tid_g; idx < SEN * 25; idx += 256) {
        int s = idx / 25, q4 = idx % 25;
        float4 w4 = ((const float4*)word_emb)[(size_t)inpb[s] * 25 + q4];
        __half2 h01 = __floats2half2_rn(w4.x, w4.y);
        __half2 h23 = __floats2half2_rn(w4.z, w4.w);
        uint2 val = make_uint2(*(uint32_t*)&h01, *(uint32_t*)&h23);
        *(uint2*)(base + (s + 1) * VROWB + q4 * 8) = val;
    }
    const int* p1b = pos1 + b * SEN;
    const int* p2b = pos2 + b * SEN;
    for (int idx = tid_g; idx < SEN * 10; idx += 256) {
        int s = idx / 10, r = idx % 10;
        int row = (r < 5) ? p1b[s] : p2b[s];
        *(__half*)(base + (s + 1) * VROWB + (100 + r) * 2) =
            __float2half_rn(pos_emb[row * 5 + (r % 5)]);
    }
}

// ============================================================================
// stage masks (half 0/1 — exact) + combined bias for ONE sample, slot `slot`.
// ============================================================================
__device__ __forceinline__ void stage_sample(
    char* smb, int b, int slot, int tid_g,
    const float* __restrict__ maskL, const float* __restrict__ maskM,
    const float* __restrict__ maskR, const float* __restrict__ conv_b)
{
    __half* mdst = (__half*)(smb + SMB_MASK) + slot * 384;
    for (int i = tid_g; i < 3 * SEN; i += 256) {
        float v = (i < 128) ? maskL[b * SEN + i]
                : (i < 256) ? maskM[b * SEN + i - 128]
                            : maskR[b * SEN + i - 256];
        mdst[i] = __float2half_rn(v);
    }
    float* cb = (float*)(smb + SMB_CB) + slot * 384;
    if (tid_g < DC) {
        float b0v = gBase[(size_t)b * 384 + tid_g];
        float b1v = gBase[(size_t)b * 384 + 128 + tid_g];
        float b2v = gBase[(size_t)b * 384 + 256 + tid_g];
        cb[tid_g]       = conv_b[tid_g] + b0v + b1v + b2v;
        cb[128 + tid_g] = b0v;
        cb[256 + tid_g] = b2v;
    }
}

// ============================================================================
// Main: 148 persistent CTAs (512 thr), TWO independent 8-warp groups (R14
// structure: warp grid 2(M) x 4(N), tile m64 x n32). NEW: sR double-buffered;
// the combine+store for sample b is DEFERRED to after the next iteration's B1,
// removing the B2 barrier (1 barrier/iter) and hiding store latency under the
// next mainloop.
// ============================================================================
__global__ __launch_bounds__(512, 1) void main_kernel(
    const int* __restrict__ inp, const int* __restrict__ pos1, const int* __restrict__ pos2,
    const float* __restrict__ maskL, const float* __restrict__ maskM, const float* __restrict__ maskR,
    const float* __restrict__ word_emb, const float* __restrict__ pos_emb,
    const float* __restrict__ conv_b, float* __restrict__ out)
{
    extern __shared__ char smb[];

    const int tid = threadIdx.x;
    const int lane = tid & 31, warp = tid >> 5;
    const int g = (warp >> 2) & 1;          // group: warps {0-3,8-11}=0, {4-7,12-15}=1
    const int warp_m = warp >> 3;           // 0/1  (m64 per warp)
    const int warp_n = warp & 3;            // 0..3 (n32 per warp)
    const int tid_g = (warp_m * 4 + warp_n) * 32 + lane;   // 0..255 within group
    const uint32_t smb_u = smem_u32(smb);

    // ---- one-time (all 512): load B (84KB), zero all 4 v tiles ----
    {
        uint32_t dst = smb_u + SMB_B;
        const uint32_t* src = gBfh;
        for (int i = tid; i < KT * 8 * 32 * 4 / 4; i += 512)
            CP16(dst + i * 16, src + i * 4);
        CP_COMMIT();
    }
    for (int i = tid; i < 4 * VH_BYTES / 4; i += 512)
        ((uint32_t*)(smb + SMB_VH))[i] = 0u;
    CP_WAIT0();
    __syncthreads();   // last CTA-wide barrier; groups diverge below

    // ---- per-group: gather+stage first sample into slot (g*2 + 0) ----
    const int b0 = blockIdx.x * 2 + g;
    gather_sample(smb, b0, g * 2, tid_g, inp, pos1, pos2, word_emb, pos_emb);
    stage_sample(smb, b0, g * 2, tid_g, maskL, maskM, maskR, conv_b);

    // ldmatrix lane addr part: row (lane&15), k-half block (lane>>4)*16B
    const uint32_t rowsel = (uint32_t)((lane & 15) * VROWB + ((lane >> 4) << 4));
    const int barid = g + 1;

    int prev_b = -1, prev_cur = 0;
    int itg = 0;
    for (int b = b0; b < SZ; b += NSTREAM, ++itg) {
        const int cur = itg & 1;
        const int slot = g * 2 + cur;

        BAR_G(barid);   // B1: sample b resident; prev epilogue's sR complete

        // ---- deferred combine+store for the PREVIOUS sample ----
        if (prev_b >= 0) {
            const float* sRp = (const float*)(smb + SMB_R) + (g * 2 + prev_cur) * 768;
            for (int t = tid_g; t < 384; t += 256) {
                float R = fmaxf(sRp[t << 1], sRp[(t << 1) + 1]);
                out[(size_t)prev_b * OUTD + t] = tanhf(R);
            }
        }

        // ---- prefetch next sample (unsynced; due by next B1) ----
        if (b + NSTREAM < SZ) {
            gather_sample(smb, b + NSTREAM, g * 2 + (cur ^ 1), tid_g, inp, pos1, pos2, word_emb, pos_emb);
            stage_sample(smb, b + NSTREAM, g * 2 + (cur ^ 1), tid_g, maskL, maskM, maskR, conv_b);
        }

        // ---- GEMM mainloop: m64 x n32 per warp ----
        float acc[4][4][4];
        #pragma unroll
        for (int mt = 0; mt < 4; mt++)
            #pragma unroll
            for (int nt = 0; nt < 4; nt++)
                #pragma unroll
                for (int r = 0; r < 4; r++) acc[mt][nt][r] = 0.f;

        const uint32_t vb = smb_u + SMB_VH + slot * VH_BYTES + rowsel;
        const uint4* sB4 = (const uint4*)(smb + SMB_B);

        #pragma unroll
        for (int tap = 0; tap < 3; tap++) {
            #pragma unroll
            for (int ktl = 0; ktl < 7; ktl++) {
                const int kt = tap * 7 + ktl;
                const uint32_t roff = (uint32_t)((warp_m * 64 + tap) * VROWB + ktl * 32);
                uint32_t am[4][4];
                LDSM4(am[0][0], am[0][1], am[0][2], am[0][3], vb + roff);
                LDSM4(am[1][0], am[1][1], am[1][2], am[1][3], vb + roff + 16 * VROWB);
                LDSM4(am[2][0], am[2][1], am[2][2], am[2][3], vb + roff + 32 * VROWB);
                LDSM4(am[3][0], am[3][1], am[3][2], am[3][3], vb + roff + 48 * VROWB);
                const uint4* bw = sB4 + kt * 256 + (warp_n * 2) * 32;
                uint4 bb0 = bw[lane];
                uint4 bb1 = bw[32 + lane];
                #pragma unroll
                for (int mt = 0; mt < 4; mt++) {
                    MMA_F16(acc[mt][0], am[mt][0], am[mt][1], am[mt][2], am[mt][3], bb0.x, bb0.y);
                    MMA_F16(acc[mt][1], am[mt][0], am[mt][1], am[mt][2], am[mt][3], bb0.z, bb0.w);
                    MMA_F16(acc[mt][2], am[mt][0], am[mt][1], am[mt][2], am[mt][3], bb1.x, bb1.y);
                    MMA_F16(acc[mt][3], am[mt][0], am[mt][1], am[mt][2], am[mt][3], bb1.z, bb1.w);
                }
            }
        }

        // ---- epilogue -> sR[slot] (no barrier; combine deferred) ----
        {
            float* sRg = (float*)(smb + SMB_R) + slot * 768;
            const __half* mp = (const __half*)(smb + SMB_MASK) + slot * 384;
            const float* cb = (const float*)(smb + SMB_CB) + slot * 384;
            float mv[3][8];
            int srow[8];
            #pragma unroll
            for (int mt = 0; mt < 4; mt++)
                #pragma unroll
                for (int rg = 0; rg < 2; rg++) {
                    int q = mt * 2 + rg;
                    int s = warp_m * 64 + mt * 16 + (lane >> 2) + rg * 8;
                    srow[q] = s;
                    mv[0][q] = __half2float(mp[s]);
                    mv[1][q] = __half2float(mp[128 + s]);
                    mv[2][q] = __half2float(mp[256 + s]);
                }
            #pragma unroll
            for (int nt = 0; nt < 4; nt++) {
                #pragma unroll
                for (int h = 0; h < 2; h++) {
                    int o = warp_n * 32 + nt * 8 + 2 * (lane & 3) + h;
                    float C = cb[o], B0v = cb[128 + o], B2v = cb[256 + o];
                    float p0 = -3.0e38f, p1 = -3.0e38f, p2 = -3.0e38f;
                    #pragma unroll
                    for (int mt = 0; mt < 4; mt++)
                        #pragma unroll
                        for (int rg = 0; rg < 2; rg++) {
                            int q = mt * 2 + rg;
                            int s = srow[q];
                            float cv = acc[mt][nt][rg * 2 + h] + C;
                            if (s == 0)   cv -= B0v;
                            if (s == 127) cv -= B2v;
                            p0 = fmaxf(p0, cv * mv[0][q]);
                            p1 = fmaxf(p1, cv * mv[1][q]);
                            p2 = fmaxf(p2, cv * mv[2][q]);
                        }
                    #pragma unroll
                    for (int off = 4; off <= 16; off <<= 1) {
                        p0 = fmaxf(p0, __shfl_xor_sync(0xffffffffu, p0, off));
                        p1 = fmaxf(p1, __shfl_xor_sync(0xffffffffu, p1, off));
                        p2 = fmaxf(p2, __shfl_xor_sync(0xffffffffu, p2, off));
                    }
                    if ((lane & 28) == 0) {
                        sRg[((0 * 128 + o) << 1) + warp_m] = p0;
                        sRg[((1 * 128 + o) << 1) + warp_m] = p1;
                        sRg[((2 * 128 + o) << 1) + warp_m] = p2;
                    }
                }
            }
        }
        prev_b = b;
        prev_cur = cur;
        // next iteration's B1 orders sR writes vs the deferred store
    }

    // ---- drain: store the final sample ----
    BAR_G(barid);
    if (prev_b >= 0) {
        const float* sRp = (const float*)(smb + SMB_R) + (g * 2 + prev_cur) * 768;
        for (int t = tid_g; t < 384; t += 256) {
            float R = fmaxf(sRp[t << 1], sRp[(t << 1) + 1]);
            out[(size_t)prev_b * OUTD + t] = tanhf(R);
        }
    }
}

// ============================================================================
extern "C" void kernel_launch(void* const* d_in, const int* in_sizes, int n_in,
                              void* d_out, int out_size) {
    const int*   inp       = (const int*)d_in[0];
    const int*   pos1      = (const int*)d_in[1];
    const int*   pos2      = (const int*)d_in[2];
    const int*   loc       = (const int*)d_in[3];
    const int*   loc_mark  = (const int*)d_in[4];
    const int*   subtype   = (const int*)d_in[5];
    const int*   argRole   = (const int*)d_in[6];
    const float* maskL     = (const float*)d_in[7];
    const float* maskM     = (const float*)d_in[8];
    const float* maskR     = (const float*)d_in[9];
    const float* word_emb  = (const float*)d_in[10];
    const float* pos_emb   = (const float*)d_in[11];
    const float* event_emb = (const float*)d_in[12];
    const float* role_emb  = (const float*)d_in[13];
    const float* conv_w    = (const float*)d_in[14];
    const float* conv_b    = (const float*)d_in[15];
    float* out = (float*)d_out;

    int prep_elems = KT * 16 * 32 * 2 + 3 * CCONST * DC;
    prep_kernel<<<(prep_elems + 255) / 256, 256>>>(conv_w);
    const_kernel<<<SZ / GS, 256>>>(loc, loc_mark, subtype, argRole,
                                   word_emb, event_emb, role_emb, out);
    cudaFuncSetAttribute(main_kernel, cudaFuncAttributeMaxDynamicSharedMemorySize, SMB_TOT);
    main_kernel<<<148, 512, SMB_TOT>>>(inp, pos1, pos2, maskL, maskM, maskR,
                                       word_emb, pos_emb, conv_b, out);
}